// round 8
// baseline (speedup 1.0000x reference)
#include <cuda_runtime.h>

#define HIDDEN 768
#define HEADS 12
#define HD 64
#define BB 8
#define LQ 512
#define LK 1024
#define QT 32
#define QPAD 65
#define CK 128
#define KT_PAD 132
#define VPAD 68

#define BM 128
#define BN 128
#define BKG 16

// Scratch (allocation-free rule: __device__ globals)
__device__ float g_q[BB * LQ * HIDDEN];
__device__ float g_k[BB * LK * HIDDEN];
__device__ float g_v[BB * LK * HIDDEN];
__device__ float g_ctx[BB * LQ * HIDDEN];
__device__ float g_tmp[BB * LQ * HIDDEN];

// ---- packed fp32x2 helpers (Blackwell FFMA2) ----
__device__ __forceinline__ void fma2(unsigned long long& d, unsigned long long a, unsigned long long b)
{
    asm("fma.rn.f32x2 %0, %1, %2, %3;" : "=l"(d) : "l"(a), "l"(b), "l"(d));
}
__device__ __forceinline__ unsigned long long dup2(float x)
{
    unsigned long long r;
    asm("mov.b64 %0, {%1, %1};" : "=l"(r) : "r"(__float_as_uint(x)));
    return r;
}
union F4U2 { float4 f4; unsigned long long u[2]; };
union U2F2 { unsigned long long u; float f[2]; };

// C[M,N] = A[M,K] @ Bm[N,K]^T + bias[N] (+ resid[M,N])
// 128x128 tile, 256 threads, 8x8 per thread via f32x2, BK=16, reg-prefetch pipeline.
__global__ __launch_bounds__(256) void gemm_nt(
    const float* __restrict__ A, const float* __restrict__ Bm,
    const float* __restrict__ bias, const float* __restrict__ resid,
    float* __restrict__ C, int M, int N, int K)
{
    __shared__ float As[BKG][BM + 4];
    __shared__ float Bs[BKG][BN + 4];
    const int tid = threadIdx.x;
    const int tx = tid & 15;         // col group: 8 cols each
    const int ty = tid >> 4;         // row group: 8 rows each
    const int row0 = blockIdx.y * BM, col0 = blockIdx.x * BN;

    const int lr = tid >> 2;         // 0..63
    const int lc = (tid & 3) * 4;    // 0,4,8,12
    const float* Aptr = A  + (size_t)(row0 + lr) * K + lc;
    const float* Bptr = Bm + (size_t)(col0 + lr) * K + lc;

    float4 pa0 = *(const float4*)(Aptr);
    float4 pa1 = *(const float4*)(Aptr + (size_t)64 * K);
    float4 pb0 = *(const float4*)(Bptr);
    float4 pb1 = *(const float4*)(Bptr + (size_t)64 * K);

    unsigned long long acc[8][4];
    #pragma unroll
    for (int i = 0; i < 8; i++)
        #pragma unroll
        for (int j = 0; j < 4; j++) acc[i][j] = 0ull;

    for (int k0 = 0; k0 < K; k0 += BKG) {
        __syncthreads();
        As[lc + 0][lr] = pa0.x; As[lc + 1][lr] = pa0.y; As[lc + 2][lr] = pa0.z; As[lc + 3][lr] = pa0.w;
        As[lc + 0][lr + 64] = pa1.x; As[lc + 1][lr + 64] = pa1.y; As[lc + 2][lr + 64] = pa1.z; As[lc + 3][lr + 64] = pa1.w;
        Bs[lc + 0][lr] = pb0.x; Bs[lc + 1][lr] = pb0.y; Bs[lc + 2][lr] = pb0.z; Bs[lc + 3][lr] = pb0.w;
        Bs[lc + 0][lr + 64] = pb1.x; Bs[lc + 1][lr + 64] = pb1.y; Bs[lc + 2][lr + 64] = pb1.z; Bs[lc + 3][lr + 64] = pb1.w;
        __syncthreads();

        const int kn = k0 + BKG;
        if (kn < K) {
            pa0 = *(const float4*)(Aptr + kn);
            pa1 = *(const float4*)(Aptr + (size_t)64 * K + kn);
            pb0 = *(const float4*)(Bptr + kn);
            pb1 = *(const float4*)(Bptr + (size_t)64 * K + kn);
        }

        #pragma unroll
        for (int kk = 0; kk < BKG; kk++) {
            float4 a0 = *(const float4*)&As[kk][ty * 8];
            float4 a1 = *(const float4*)&As[kk][ty * 8 + 4];
            F4U2 b0, b1;
            b0.f4 = *(const float4*)&Bs[kk][tx * 8];
            b1.f4 = *(const float4*)&Bs[kk][tx * 8 + 4];
            unsigned long long ad[8];
            ad[0] = dup2(a0.x); ad[1] = dup2(a0.y); ad[2] = dup2(a0.z); ad[3] = dup2(a0.w);
            ad[4] = dup2(a1.x); ad[5] = dup2(a1.y); ad[6] = dup2(a1.z); ad[7] = dup2(a1.w);
            #pragma unroll
            for (int i = 0; i < 8; i++) {
                fma2(acc[i][0], ad[i], b0.u[0]);
                fma2(acc[i][1], ad[i], b0.u[1]);
                fma2(acc[i][2], ad[i], b1.u[0]);
                fma2(acc[i][3], ad[i], b1.u[1]);
            }
        }
    }

    const int c = col0 + tx * 8;
    float4 bb0 = *(const float4*)(bias + c);
    float4 bb1 = *(const float4*)(bias + c + 4);
    #pragma unroll
    for (int i = 0; i < 8; i++) {
        const int r = row0 + ty * 8 + i;
        U2F2 u0, u1, u2, u3;
        u0.u = acc[i][0]; u1.u = acc[i][1]; u2.u = acc[i][2]; u3.u = acc[i][3];
        float4 o0, o1;
        o0.x = u0.f[0] + bb0.x; o0.y = u0.f[1] + bb0.y;
        o0.z = u1.f[0] + bb0.z; o0.w = u1.f[1] + bb0.w;
        o1.x = u2.f[0] + bb1.x; o1.y = u2.f[1] + bb1.y;
        o1.z = u3.f[0] + bb1.z; o1.w = u3.f[1] + bb1.w;
        if (resid) {
            float4 r0v = *(const float4*)(resid + (size_t)r * N + c);
            float4 r1v = *(const float4*)(resid + (size_t)r * N + c + 4);
            o0.x += r0v.x; o0.y += r0v.y; o0.z += r0v.z; o0.w += r0v.w;
            o1.x += r1v.x; o1.y += r1v.y; o1.z += r1v.z; o1.w += r1v.w;
        }
        *(float4*)(C + (size_t)r * N + c) = o0;
        *(float4*)(C + (size_t)r * N + c + 4) = o1;
    }
}

// Fused attention per (q-tile of 32 rows, head, batch), 512 threads:
// scores (QK^T/8 + mask) -> softmax -> write probs -> ctx = P@V
__global__ __launch_bounds__(512) void attn_kernel(
    const float* __restrict__ Qp, const float* __restrict__ Kp,
    const float* __restrict__ Vp, const float* __restrict__ mask,
    float* __restrict__ probs, float* __restrict__ ctx)
{
    extern __shared__ float smem[];
    float* Sm     = smem;                      // QT*LK           (32768)
    float* Qs     = Sm + QT * LK;              // QT*QPAD         (2080)
    float* KVs    = Qs + QT * QPAD;            // 8704 floats (max of 64*KT_PAD=8448, 128*VPAD=8704)
    float* msk    = KVs + 8704;                // LK              (1024)
    float* rowinv = msk + LK;                  // QT              (32)

    const int tid = threadIdx.x;
    const int q0 = blockIdx.x * QT;
    const int h  = blockIdx.y;
    const int b  = blockIdx.z;

    // stage mask row
    for (int i = tid; i < LK; i += 512) msk[i] = mask[b * LK + i];

    // load Q tile [QT][64] (1 float4 per thread)
    {
        int r = tid >> 4, d = (tid & 15) * 4;
        float4 qv = *(const float4*)(Qp + (size_t)(b * LQ + q0 + r) * HIDDEN + h * HD + d);
        Qs[r * QPAD + d + 0] = qv.x;
        Qs[r * QPAD + d + 1] = qv.y;
        Qs[r * QPAD + d + 2] = qv.z;
        Qs[r * QPAD + d + 3] = qv.w;
    }

    const int row = tid >> 4;   // 0..31
    const int cg  = tid & 15;   // 0..15

    // ---- scores: 128-wide K chunks, 1 row x 8 cols per thread ----
    for (int c0 = 0; c0 < LK; c0 += CK) {
        __syncthreads();
        #pragma unroll
        for (int i = 0; i < 4; i++) {
            int idx4 = tid + i * 512;          // 2048 float4 = 128x64
            int r = idx4 >> 4, d = (idx4 & 15) * 4;
            float4 kv = *(const float4*)(Kp + (size_t)(b * LK + c0 + r) * HIDDEN + h * HD + d);
            KVs[(d + 0) * KT_PAD + r] = kv.x;
            KVs[(d + 1) * KT_PAD + r] = kv.y;
            KVs[(d + 2) * KT_PAD + r] = kv.z;
            KVs[(d + 3) * KT_PAD + r] = kv.w;
        }
        __syncthreads();

        unsigned long long acc2[4] = {0ull, 0ull, 0ull, 0ull};
        #pragma unroll 8
        for (int d = 0; d < HD; d++) {
            unsigned long long qa = dup2(Qs[row * QPAD + d]);
            F4U2 k0, k1;
            k0.f4 = *(const float4*)&KVs[d * KT_PAD + cg * 8];
            k1.f4 = *(const float4*)&KVs[d * KT_PAD + cg * 8 + 4];
            fma2(acc2[0], qa, k0.u[0]);
            fma2(acc2[1], qa, k0.u[1]);
            fma2(acc2[2], qa, k1.u[0]);
            fma2(acc2[3], qa, k1.u[1]);
        }
        const int cbase = c0 + cg * 8;
        #pragma unroll
        for (int j = 0; j < 4; j++) {
            U2F2 u; u.u = acc2[j];
            Sm[row * LK + cbase + 2 * j + 0] = u.f[0] * 0.125f + msk[cbase + 2 * j + 0];
            Sm[row * LK + cbase + 2 * j + 1] = u.f[1] * 0.125f + msk[cbase + 2 * j + 1];
        }
    }
    __syncthreads();

    // ---- softmax: warp w owns rows 2w, 2w+1 ----
    {
        const int w = tid >> 5, lane = tid & 31;
        #pragma unroll
        for (int rr = 0; rr < 2; rr++) {
            int r = w * 2 + rr;
            float m = -1e30f;
            #pragma unroll
            for (int c4 = lane; c4 < LK / 4; c4 += 32) {
                float4 v = *(const float4*)&Sm[r * LK + c4 * 4];
                m = fmaxf(m, fmaxf(fmaxf(v.x, v.y), fmaxf(v.z, v.w)));
            }
            #pragma unroll
            for (int off = 16; off; off >>= 1) m = fmaxf(m, __shfl_xor_sync(0xffffffffu, m, off));
            float s = 0.f;
            #pragma unroll
            for (int c4 = lane; c4 < LK / 4; c4 += 32) {
                float4 v = *(const float4*)&Sm[r * LK + c4 * 4];
                v.x = __expf(v.x - m); v.y = __expf(v.y - m);
                v.z = __expf(v.z - m); v.w = __expf(v.w - m);
                *(float4*)&Sm[r * LK + c4 * 4] = v;
                s += v.x + v.y + v.z + v.w;
            }
            #pragma unroll
            for (int off = 16; off; off >>= 1) s += __shfl_xor_sync(0xffffffffu, s, off);
            if (lane == 0) rowinv[r] = 1.f / s;
        }
    }
    __syncthreads();

    // ---- normalize + write probs (float4, coalesced) ----
    {
        float* prow = probs + ((size_t)((b * HEADS + h) * LQ + q0)) * LK;
        #pragma unroll
        for (int i4 = tid; i4 < QT * LK / 4; i4 += 512) {
            float inv = rowinv[i4 >> 8];
            float4 p = *(const float4*)&Sm[i4 * 4];
            p.x *= inv; p.y *= inv; p.z *= inv; p.w *= inv;
            *(float4*)&Sm[i4 * 4] = p;
            *(float4*)&prow[i4 * 4] = p;
        }
    }

    // ---- ctx = P @ V : 128-row V chunks, 1 row x 4 cols per thread ----
    unsigned long long accv[2] = {0ull, 0ull};
    for (int c0 = 0; c0 < LK; c0 += CK) {
        __syncthreads();
        #pragma unroll
        for (int i = 0; i < 4; i++) {
            int idx4 = tid + i * 512;
            int r = idx4 >> 4, d = (idx4 & 15) * 4;
            float4 vv = *(const float4*)(Vp + (size_t)(b * LK + c0 + r) * HIDDEN + h * HD + d);
            *(float4*)&KVs[r * VPAD + d] = vv;
        }
        __syncthreads();
        #pragma unroll 8
        for (int k = 0; k < CK; k++) {
            unsigned long long p = dup2(Sm[row * LK + c0 + k]);
            F4U2 vv;
            vv.f4 = *(const float4*)&KVs[k * VPAD + cg * 4];
            fma2(accv[0], p, vv.u[0]);
            fma2(accv[1], p, vv.u[1]);
        }
    }
    {
        U2F2 lo, hi; lo.u = accv[0]; hi.u = accv[1];
        float4 o; o.x = lo.f[0]; o.y = lo.f[1]; o.z = hi.f[0]; o.w = hi.f[1];
        *(float4*)(ctx + (size_t)(b * LQ + q0 + row) * HIDDEN + h * HD + cg * 4) = o;
    }
}

// Row LayerNorm over 768; one block of 256 threads per row.
__global__ void out_ln(const float* __restrict__ X, const float* __restrict__ gamma,
                       const float* __restrict__ beta, float* __restrict__ out)
{
    const int row = blockIdx.x;
    const int tid = threadIdx.x;
    const float* x = X + (size_t)row * HIDDEN;

    float v[3];
    float s = 0.f, s2 = 0.f;
    #pragma unroll
    for (int i = 0; i < 3; i++) {
        v[i] = x[tid + i * 256];
        s += v[i];
        s2 += v[i] * v[i];
    }
    const int w = tid >> 5, lane = tid & 31;
    #pragma unroll
    for (int off = 16; off; off >>= 1) {
        s  += __shfl_xor_sync(0xffffffffu, s,  off);
        s2 += __shfl_xor_sync(0xffffffffu, s2, off);
    }
    __shared__ float rs[8], rs2[8];
    __shared__ float mu_s, inv_s;
    if (lane == 0) { rs[w] = s; rs2[w] = s2; }
    __syncthreads();
    if (tid == 0) {
        float S = 0.f, S2 = 0.f;
        #pragma unroll
        for (int i = 0; i < 8; i++) { S += rs[i]; S2 += rs2[i]; }
        float mu = S * (1.0f / HIDDEN);
        float var = S2 * (1.0f / HIDDEN) - mu * mu;
        mu_s = mu;
        inv_s = rsqrtf(var + 1e-12f);
    }
    __syncthreads();
    const float mu = mu_s, inv = inv_s;
    #pragma unroll
    for (int i = 0; i < 3; i++) {
        int c = tid + i * 256;
        out[(size_t)row * HIDDEN + c] = (v[i] - mu) * inv * gamma[c] + beta[c];
    }
}

extern "C" void kernel_launch(void* const* d_in, const int* in_sizes, int n_in,
                              void* d_out, int out_size)
{
    const float* query = (const float*)d_in[0];
    const float* key   = (const float*)d_in[1];
    const float* value = (const float*)d_in[2];
    const float* mask  = (const float*)d_in[3];
    // d_in[4] = q_attention_mask (unused by reference math)
    const float* Wq = (const float*)d_in[5];
    const float* bq = (const float*)d_in[6];
    const float* Wk = (const float*)d_in[7];
    const float* bk = (const float*)d_in[8];
    const float* Wv = (const float*)d_in[9];
    const float* bv = (const float*)d_in[10];
    const float* Wo = (const float*)d_in[11];
    const float* bo = (const float*)d_in[12];
    const float* gamma = (const float*)d_in[13];
    const float* beta  = (const float*)d_in[14];

    float* out   = (float*)d_out;
    float* probs = out + (size_t)BB * LQ * HIDDEN;

    float *qp, *kp, *vp, *ctx, *tmp;
    cudaGetSymbolAddress((void**)&qp,  g_q);
    cudaGetSymbolAddress((void**)&kp,  g_k);
    cudaGetSymbolAddress((void**)&vp,  g_v);
    cudaGetSymbolAddress((void**)&ctx, g_ctx);
    cudaGetSymbolAddress((void**)&tmp, g_tmp);

    // Q/K/V projections
    gemm_nt<<<dim3(HIDDEN / BN, (BB * LQ) / BM), 256>>>(query, Wq, bq, nullptr, qp, BB * LQ, HIDDEN, HIDDEN);
    gemm_nt<<<dim3(HIDDEN / BN, (BB * LK) / BM), 256>>>(key,   Wk, bk, nullptr, kp, BB * LK, HIDDEN, HIDDEN);
    gemm_nt<<<dim3(HIDDEN / BN, (BB * LK) / BM), 256>>>(value, Wv, bv, nullptr, vp, BB * LK, HIDDEN, HIDDEN);

    // Fused attention (512 threads, ~178 KB smem)
    size_t smem = (size_t)(QT * LK + QT * QPAD + 8704 + LK + QT) * sizeof(float);
    cudaFuncSetAttribute(attn_kernel, cudaFuncAttributeMaxDynamicSharedMemorySize, (int)smem);
    attn_kernel<<<dim3(LQ / QT, HEADS, BB), 512, smem>>>(qp, kp, vp, mask, probs, ctx);

    // Output projection + bias + residual, then LayerNorm
    gemm_nt<<<dim3(HIDDEN / BN, (BB * LQ) / BM), 256>>>(ctx, Wo, bo, query, tmp, BB * LQ, HIDDEN, HIDDEN);
    out_ln<<<BB * LQ, 256>>>(tmp, gamma, beta, out);
}

// round 13
// speedup vs baseline: 1.6778x; 1.6778x over previous
#include <cuda_runtime.h>

#define HIDDEN 768
#define HEADS 12
#define HD 64
#define BB 8
#define LQ 512
#define LK 1024
#define QT 32
#define QPITCH 68
#define KVPITCH 68
#define CK 256

#define BM 128
#define BN 128
#define BKG 16

// Scratch (allocation-free rule: __device__ globals)
__device__ float g_q[BB * LQ * HIDDEN];
__device__ float g_k[BB * LK * HIDDEN];
__device__ float g_v[BB * LK * HIDDEN];
__device__ float g_ctx[BB * LQ * HIDDEN];
__device__ float g_tmp[BB * LQ * HIDDEN];

// ---- packed fp32x2 helpers (Blackwell FFMA2) ----
__device__ __forceinline__ void fma2(unsigned long long& d, unsigned long long a, unsigned long long b)
{
    asm("fma.rn.f32x2 %0, %1, %2, %3;" : "=l"(d) : "l"(a), "l"(b), "l"(d));
}
__device__ __forceinline__ unsigned long long dup2(float x)
{
    unsigned long long r;
    asm("mov.b64 %0, {%1, %1};" : "=l"(r) : "r"(__float_as_uint(x)));
    return r;
}
union F4U2 { float4 f4; unsigned long long u[2]; float f[4]; };
union U2F2 { unsigned long long u; float f[2]; };

// C[M,N] = A[M,K] @ Bm[N,K]^T + bias[N] (+ resid[M,N])
// 128x128 tile, 256 threads, 8x8 per thread via f32x2, BK=16, reg-prefetch pipeline.
__global__ __launch_bounds__(256) void gemm_nt(
    const float* __restrict__ A, const float* __restrict__ Bm,
    const float* __restrict__ bias, const float* __restrict__ resid,
    float* __restrict__ C, int M, int N, int K)
{
    __shared__ float As[BKG][BM + 4];
    __shared__ float Bs[BKG][BN + 4];
    const int tid = threadIdx.x;
    const int tx = tid & 15;
    const int ty = tid >> 4;
    const int row0 = blockIdx.y * BM, col0 = blockIdx.x * BN;

    const int lr = tid >> 2;
    const int lc = (tid & 3) * 4;
    const float* Aptr = A  + (size_t)(row0 + lr) * K + lc;
    const float* Bptr = Bm + (size_t)(col0 + lr) * K + lc;

    float4 pa0 = *(const float4*)(Aptr);
    float4 pa1 = *(const float4*)(Aptr + (size_t)64 * K);
    float4 pb0 = *(const float4*)(Bptr);
    float4 pb1 = *(const float4*)(Bptr + (size_t)64 * K);

    unsigned long long acc[8][4];
    #pragma unroll
    for (int i = 0; i < 8; i++)
        #pragma unroll
        for (int j = 0; j < 4; j++) acc[i][j] = 0ull;

    for (int k0 = 0; k0 < K; k0 += BKG) {
        __syncthreads();
        As[lc + 0][lr] = pa0.x; As[lc + 1][lr] = pa0.y; As[lc + 2][lr] = pa0.z; As[lc + 3][lr] = pa0.w;
        As[lc + 0][lr + 64] = pa1.x; As[lc + 1][lr + 64] = pa1.y; As[lc + 2][lr + 64] = pa1.z; As[lc + 3][lr + 64] = pa1.w;
        Bs[lc + 0][lr] = pb0.x; Bs[lc + 1][lr] = pb0.y; Bs[lc + 2][lr] = pb0.z; Bs[lc + 3][lr] = pb0.w;
        Bs[lc + 0][lr + 64] = pb1.x; Bs[lc + 1][lr + 64] = pb1.y; Bs[lc + 2][lr + 64] = pb1.z; Bs[lc + 3][lr + 64] = pb1.w;
        __syncthreads();

        const int kn = k0 + BKG;
        if (kn < K) {
            pa0 = *(const float4*)(Aptr + kn);
            pa1 = *(const float4*)(Aptr + (size_t)64 * K + kn);
            pb0 = *(const float4*)(Bptr + kn);
            pb1 = *(const float4*)(Bptr + (size_t)64 * K + kn);
        }

        #pragma unroll
        for (int kk = 0; kk < BKG; kk++) {
            float4 a0 = *(const float4*)&As[kk][ty * 8];
            float4 a1 = *(const float4*)&As[kk][ty * 8 + 4];
            F4U2 b0, b1;
            b0.f4 = *(const float4*)&Bs[kk][tx * 8];
            b1.f4 = *(const float4*)&Bs[kk][tx * 8 + 4];
            unsigned long long ad[8];
            ad[0] = dup2(a0.x); ad[1] = dup2(a0.y); ad[2] = dup2(a0.z); ad[3] = dup2(a0.w);
            ad[4] = dup2(a1.x); ad[5] = dup2(a1.y); ad[6] = dup2(a1.z); ad[7] = dup2(a1.w);
            #pragma unroll
            for (int i = 0; i < 8; i++) {
                fma2(acc[i][0], ad[i], b0.u[0]);
                fma2(acc[i][1], ad[i], b0.u[1]);
                fma2(acc[i][2], ad[i], b1.u[0]);
                fma2(acc[i][3], ad[i], b1.u[1]);
            }
        }
    }

    const int c = col0 + tx * 8;
    float4 bb0 = *(const float4*)(bias + c);
    float4 bb1 = *(const float4*)(bias + c + 4);
    #pragma unroll
    for (int i = 0; i < 8; i++) {
        const int r = row0 + ty * 8 + i;
        U2F2 u0, u1, u2, u3;
        u0.u = acc[i][0]; u1.u = acc[i][1]; u2.u = acc[i][2]; u3.u = acc[i][3];
        float4 o0, o1;
        o0.x = u0.f[0] + bb0.x; o0.y = u0.f[1] + bb0.y;
        o0.z = u1.f[0] + bb0.z; o0.w = u1.f[1] + bb0.w;
        o1.x = u2.f[0] + bb1.x; o1.y = u2.f[1] + bb1.y;
        o1.z = u3.f[0] + bb1.z; o1.w = u3.f[1] + bb1.w;
        if (resid) {
            float4 r0v = *(const float4*)(resid + (size_t)r * N + c);
            float4 r1v = *(const float4*)(resid + (size_t)r * N + c + 4);
            o0.x += r0v.x; o0.y += r0v.y; o0.z += r0v.z; o0.w += r0v.w;
            o1.x += r1v.x; o1.y += r1v.y; o1.z += r1v.z; o1.w += r1v.w;
        }
        *(float4*)(C + (size_t)r * N + c) = o0;
        *(float4*)(C + (size_t)r * N + c + 4) = o1;
    }
}

// Fused attention per (q-tile of 32 rows, head, batch), 256 threads.
// Register-blocked to minimize smem crossbar traffic (L1 was 86% at R8).
__global__ __launch_bounds__(256) void attn_kernel(
    const float* __restrict__ Qp, const float* __restrict__ Kp,
    const float* __restrict__ Vp, const float* __restrict__ mask,
    float* __restrict__ probs, float* __restrict__ ctx)
{
    extern __shared__ float smem[];
    float* Sm     = smem;                       // QT*LK = 32768
    float* Qs     = Sm + QT * LK;               // QT*QPITCH = 2176
    float* KVs    = Qs + QT * QPITCH;           // CK*KVPITCH = 17408
    float* red    = KVs + CK * KVPITCH;         // QT*HD = 2048
    float* rowinv = red + QT * HD;              // QT

    const int tid = threadIdx.x;
    const int q0 = blockIdx.x * QT;
    const int h  = blockIdx.y;
    const int b  = blockIdx.z;

    // ---- load Q tile [QT][64] into Qs (pitch 68), 2 float4 per thread ----
    #pragma unroll
    for (int i = 0; i < 2; i++) {
        int idx4 = tid + i * 256;               // 512 float4 = 32x64
        int r = idx4 >> 4, d = (idx4 & 15) * 4;
        float4 qv = *(const float4*)(Qp + (size_t)(b * LQ + q0 + r) * HIDDEN + h * HD + d);
        *(float4*)&Qs[r * QPITCH + d] = qv;
    }

    // ================= scores =================
    // thread tile: 4 rows x 8 cols (cols = cg + 32*j), d-vectorized fma2.
    const int rg = tid >> 5;    // 0..7 -> rows rg*4..rg*4+3
    const int cg = tid & 31;    // 0..31

    for (int c0 = 0; c0 < LK; c0 += CK) {
        __syncthreads();
        // fill K chunk [CK][64] row-major pitch 68 (contiguous copy, no transpose)
        #pragma unroll
        for (int i = 0; i < 16; i++) {
            int idx4 = tid + i * 256;           // 4096 float4 = 256x64
            int r = idx4 >> 4, d = (idx4 & 15) * 4;
            float4 kv = *(const float4*)(Kp + (size_t)(b * LK + c0 + r) * HIDDEN + h * HD + d);
            *(float4*)&KVs[r * KVPITCH + d] = kv;
        }
        __syncthreads();

        unsigned long long parts[4][8];
        #pragma unroll
        for (int i = 0; i < 4; i++)
            #pragma unroll
            for (int j = 0; j < 8; j++) parts[i][j] = 0ull;

        for (int d0 = 0; d0 < HD; d0 += 4) {
            F4U2 q4[4];
            #pragma unroll
            for (int i = 0; i < 4; i++)
                q4[i].f4 = *(const float4*)&Qs[(rg * 4 + i) * QPITCH + d0];
            #pragma unroll
            for (int j = 0; j < 8; j++) {
                F4U2 k4;
                k4.f4 = *(const float4*)&KVs[(cg + 32 * j) * KVPITCH + d0];
                #pragma unroll
                for (int i = 0; i < 4; i++) {
                    fma2(parts[i][j], q4[i].u[0], k4.u[0]);
                    fma2(parts[i][j], q4[i].u[1], k4.u[1]);
                }
            }
        }
        // horizontal add + scale + mask -> Sm
        #pragma unroll
        for (int j = 0; j < 8; j++) {
            int c = c0 + cg + 32 * j;
            float mv = mask[b * LK + c];
            #pragma unroll
            for (int i = 0; i < 4; i++) {
                U2F2 u; u.u = parts[i][j];
                Sm[(rg * 4 + i) * LK + c] = (u.f[0] + u.f[1]) * 0.125f + mv;
            }
        }
    }
    __syncthreads();

    // ---- softmax: warp w owns rows 4w..4w+3 ----
    {
        const int w = tid >> 5, lane = tid & 31;
        #pragma unroll
        for (int rr = 0; rr < 4; rr++) {
            int r = w * 4 + rr;
            float m = -1e30f;
            #pragma unroll
            for (int c4 = lane; c4 < LK / 4; c4 += 32) {
                float4 v = *(const float4*)&Sm[r * LK + c4 * 4];
                m = fmaxf(m, fmaxf(fmaxf(v.x, v.y), fmaxf(v.z, v.w)));
            }
            #pragma unroll
            for (int off = 16; off; off >>= 1) m = fmaxf(m, __shfl_xor_sync(0xffffffffu, m, off));
            float s = 0.f;
            #pragma unroll
            for (int c4 = lane; c4 < LK / 4; c4 += 32) {
                float4 v = *(const float4*)&Sm[r * LK + c4 * 4];
                v.x = __expf(v.x - m); v.y = __expf(v.y - m);
                v.z = __expf(v.z - m); v.w = __expf(v.w - m);
                *(float4*)&Sm[r * LK + c4 * 4] = v;
                s += v.x + v.y + v.z + v.w;
            }
            #pragma unroll
            for (int off = 16; off; off >>= 1) s += __shfl_xor_sync(0xffffffffu, s, off);
            if (lane == 0) rowinv[r] = 1.f / s;
        }
    }
    __syncthreads();

    // ---- normalize + write probs (float4, coalesced) ----
    {
        float* prow = probs + ((size_t)((b * HEADS + h) * LQ + q0)) * LK;
        #pragma unroll
        for (int i4 = tid; i4 < QT * LK / 4; i4 += 256) {
            float inv = rowinv[i4 >> 8];
            float4 p = *(const float4*)&Sm[i4 * 4];
            p.x *= inv; p.y *= inv; p.z *= inv; p.w *= inv;
            *(float4*)&Sm[i4 * 4] = p;
            *(float4*)&prow[i4 * 4] = p;
        }
    }

    // ================= ctx = P @ V =================
    // k-split x2: group g (128 thr) handles k in [c0 + g*128, +128) per 256-chunk.
    // thread tile: 4 rows x 4 cols.
    const int grp  = tid >> 7;          // 0..1
    const int gtid = tid & 127;
    const int rgv  = gtid >> 4;         // 0..7 -> rows rgv*4..+3
    const int cgv  = gtid & 15;         // 0..15 -> cols cgv*4..+3

    unsigned long long accv[4][2];
    #pragma unroll
    for (int i = 0; i < 4; i++) { accv[i][0] = 0ull; accv[i][1] = 0ull; }

    for (int c0 = 0; c0 < LK; c0 += CK) {
        __syncthreads();
        // fill V chunk [CK][64] pitch 68 (contiguous copy)
        #pragma unroll
        for (int i = 0; i < 16; i++) {
            int idx4 = tid + i * 256;
            int r = idx4 >> 4, d = (idx4 & 15) * 4;
            float4 vv = *(const float4*)(Vp + (size_t)(b * LK + c0 + r) * HIDDEN + h * HD + d);
            *(float4*)&KVs[r * KVPITCH + d] = vv;
        }
        __syncthreads();

        const int kbase = grp * 128;
        for (int kk = 0; kk < 128; kk += 4) {
            F4U2 p4[4];
            #pragma unroll
            for (int i = 0; i < 4; i++)
                p4[i].f4 = *(const float4*)&Sm[(rgv * 4 + i) * LK + c0 + kbase + kk];
            #pragma unroll
            for (int t = 0; t < 4; t++) {
                F4U2 vv;
                vv.f4 = *(const float4*)&KVs[(kbase + kk + t) * KVPITCH + cgv * 4];
                #pragma unroll
                for (int i = 0; i < 4; i++) {
                    unsigned long long pd = dup2(p4[i].f[t]);
                    fma2(accv[i][0], pd, vv.u[0]);
                    fma2(accv[i][1], pd, vv.u[1]);
                }
            }
        }
    }
    __syncthreads();

    // cross-group reduction: grp0 stages partials, grp1 adds + writes ctx
    if (grp == 0) {
        #pragma unroll
        for (int i = 0; i < 4; i++) {
            U2F2 lo, hi; lo.u = accv[i][0]; hi.u = accv[i][1];
            float4 o; o.x = lo.f[0]; o.y = lo.f[1]; o.z = hi.f[0]; o.w = hi.f[1];
            *(float4*)&red[(rgv * 4 + i) * HD + cgv * 4] = o;
        }
    }
    __syncthreads();
    if (grp == 1) {
        #pragma unroll
        for (int i = 0; i < 4; i++) {
            U2F2 lo, hi; lo.u = accv[i][0]; hi.u = accv[i][1];
            float4 p = *(const float4*)&red[(rgv * 4 + i) * HD + cgv * 4];
            float4 o;
            o.x = lo.f[0] + p.x; o.y = lo.f[1] + p.y;
            o.z = hi.f[0] + p.z; o.w = hi.f[1] + p.w;
            *(float4*)(ctx + (size_t)(b * LQ + q0 + rgv * 4 + i) * HIDDEN + h * HD + cgv * 4) = o;
        }
    }
}

// Row LayerNorm over 768; one block of 256 threads per row.
__global__ void out_ln(const float* __restrict__ X, const float* __restrict__ gamma,
                       const float* __restrict__ beta, float* __restrict__ out)
{
    const int row = blockIdx.x;
    const int tid = threadIdx.x;
    const float* x = X + (size_t)row * HIDDEN;

    float v[3];
    float s = 0.f, s2 = 0.f;
    #pragma unroll
    for (int i = 0; i < 3; i++) {
        v[i] = x[tid + i * 256];
        s += v[i];
        s2 += v[i] * v[i];
    }
    const int w = tid >> 5, lane = tid & 31;
    #pragma unroll
    for (int off = 16; off; off >>= 1) {
        s  += __shfl_xor_sync(0xffffffffu, s,  off);
        s2 += __shfl_xor_sync(0xffffffffu, s2, off);
    }
    __shared__ float rs[8], rs2[8];
    __shared__ float mu_s, inv_s;
    if (lane == 0) { rs[w] = s; rs2[w] = s2; }
    __syncthreads();
    if (tid == 0) {
        float S = 0.f, S2 = 0.f;
        #pragma unroll
        for (int i = 0; i < 8; i++) { S += rs[i]; S2 += rs2[i]; }
        float mu = S * (1.0f / HIDDEN);
        float var = S2 * (1.0f / HIDDEN) - mu * mu;
        mu_s = mu;
        inv_s = rsqrtf(var + 1e-12f);
    }
    __syncthreads();
    const float mu = mu_s, inv = inv_s;
    #pragma unroll
    for (int i = 0; i < 3; i++) {
        int c = tid + i * 256;
        out[(size_t)row * HIDDEN + c] = (v[i] - mu) * inv * gamma[c] + beta[c];
    }
}

extern "C" void kernel_launch(void* const* d_in, const int* in_sizes, int n_in,
                              void* d_out, int out_size)
{
    const float* query = (const float*)d_in[0];
    const float* key   = (const float*)d_in[1];
    const float* value = (const float*)d_in[2];
    const float* mask  = (const float*)d_in[3];
    // d_in[4] = q_attention_mask (unused by reference math)
    const float* Wq = (const float*)d_in[5];
    const float* bq = (const float*)d_in[6];
    const float* Wk = (const float*)d_in[7];
    const float* bk = (const float*)d_in[8];
    const float* Wv = (const float*)d_in[9];
    const float* bv = (const float*)d_in[10];
    const float* Wo = (const float*)d_in[11];
    const float* bo = (const float*)d_in[12];
    const float* gamma = (const float*)d_in[13];
    const float* beta  = (const float*)d_in[14];

    float* out   = (float*)d_out;
    float* probs = out + (size_t)BB * LQ * HIDDEN;

    float *qp, *kp, *vp, *ctx, *tmp;
    cudaGetSymbolAddress((void**)&qp,  g_q);
    cudaGetSymbolAddress((void**)&kp,  g_k);
    cudaGetSymbolAddress((void**)&vp,  g_v);
    cudaGetSymbolAddress((void**)&ctx, g_ctx);
    cudaGetSymbolAddress((void**)&tmp, g_tmp);

    // Q/K/V projections
    gemm_nt<<<dim3(HIDDEN / BN, (BB * LQ) / BM), 256>>>(query, Wq, bq, nullptr, qp, BB * LQ, HIDDEN, HIDDEN);
    gemm_nt<<<dim3(HIDDEN / BN, (BB * LK) / BM), 256>>>(key,   Wk, bk, nullptr, kp, BB * LK, HIDDEN, HIDDEN);
    gemm_nt<<<dim3(HIDDEN / BN, (BB * LK) / BM), 256>>>(value, Wv, bv, nullptr, vp, BB * LK, HIDDEN, HIDDEN);

    // Fused attention (256 threads, ~213 KB smem)
    size_t smem = (size_t)(QT * LK + QT * QPITCH + CK * KVPITCH + QT * HD + QT) * sizeof(float);
    cudaFuncSetAttribute(attn_kernel, cudaFuncAttributeMaxDynamicSharedMemorySize, (int)smem);
    attn_kernel<<<dim3(LQ / QT, HEADS, BB), 256, smem>>>(qp, kp, vp, mask, probs, ctx);

    // Output projection + bias + residual, then LayerNorm
    gemm_nt<<<dim3(HIDDEN / BN, (BB * LQ) / BM), 256>>>(ctx, Wo, bo, query, tmp, BB * LQ, HIDDEN, HIDDEN);
    out_ln<<<BB * LQ, 256>>>(tmp, gamma, beta, out);
}

// round 16
// speedup vs baseline: 2.6783x; 1.5964x over previous
#include <cuda_runtime.h>
#include <cuda_bf16.h>
#include <cstdint>

#define HIDDEN 768
#define HEADS 12
#define HD 64
#define BB 8
#define LQ 512
#define LK 1024
#define QT 32
#define QPITCH 68
#define KVPITCH 68
#define CK 256

// mma GEMM tiling: 128x128 CTA tile, 8 warps (2 x 4), warp = 64x32, k-chunk 32
#define SPITCH 40            // smem row pitch in bf16 (80 B)

// Scratch (allocation-free rule: __device__ globals)
__device__ float g_q[BB * LQ * HIDDEN];
__device__ float g_k[BB * LK * HIDDEN];
__device__ float g_v[BB * LK * HIDDEN];
__device__ float g_ctx[BB * LQ * HIDDEN];
__device__ float g_tmp[BB * LQ * HIDDEN];

// ---- packed fp32x2 helpers (Blackwell FFMA2) ----
__device__ __forceinline__ void fma2(unsigned long long& d, unsigned long long a, unsigned long long b)
{
    asm("fma.rn.f32x2 %0, %1, %2, %3;" : "=l"(d) : "l"(a), "l"(b), "l"(d));
}
__device__ __forceinline__ unsigned long long dup2(float x)
{
    unsigned long long r;
    asm("mov.b64 %0, {%1, %1};" : "=l"(r) : "r"(__float_as_uint(x)));
    return r;
}
union F4U2 { float4 f4; unsigned long long u[2]; float f[4]; };
union U2F2 { unsigned long long u; float f[2]; };

__device__ __forceinline__ uint32_t smem_u32(const void* p)
{
    uint32_t a;
    asm("{ .reg .u64 t; cvta.to.shared.u64 t, %1; cvt.u32.u64 %0, t; }" : "=r"(a) : "l"(p));
    return a;
}

// ---- mma.sync helpers (legacy HMMA path; compiles for plain compute_103) ----
__device__ __forceinline__ void ldsm4(uint32_t* r, uint32_t addr)
{
    asm volatile("ldmatrix.sync.aligned.m8n8.x4.shared.b16 {%0,%1,%2,%3}, [%4];"
                 : "=r"(r[0]), "=r"(r[1]), "=r"(r[2]), "=r"(r[3]) : "r"(addr));
}
__device__ __forceinline__ void ldsm2(uint32_t* r, uint32_t addr)
{
    asm volatile("ldmatrix.sync.aligned.m8n8.x2.shared.b16 {%0,%1}, [%2];"
                 : "=r"(r[0]), "=r"(r[1]) : "r"(addr));
}
__device__ __forceinline__ void mma16816(float* d, const uint32_t* a, const uint32_t* b)
{
    asm volatile(
        "mma.sync.aligned.m16n8k16.row.col.f32.bf16.bf16.f32 "
        "{%0,%1,%2,%3}, {%4,%5,%6,%7}, {%8,%9}, {%0,%1,%2,%3};"
        : "+f"(d[0]), "+f"(d[1]), "+f"(d[2]), "+f"(d[3])
        : "r"(a[0]), "r"(a[1]), "r"(a[2]), "r"(a[3]), "r"(b[0]), "r"(b[1]));
}
__device__ __forceinline__ void cvt_split(float4 v, uint2& h, uint2& l)
{
    __nv_bfloat16 h0 = __float2bfloat16(v.x), h1 = __float2bfloat16(v.y);
    __nv_bfloat16 h2 = __float2bfloat16(v.z), h3 = __float2bfloat16(v.w);
    __nv_bfloat16 l0 = __float2bfloat16(v.x - __bfloat162float(h0));
    __nv_bfloat16 l1 = __float2bfloat16(v.y - __bfloat162float(h1));
    __nv_bfloat16 l2 = __float2bfloat16(v.z - __bfloat162float(h2));
    __nv_bfloat16 l3 = __float2bfloat16(v.w - __bfloat162float(h3));
    __nv_bfloat162 h01 = __halves2bfloat162(h0, h1), h23 = __halves2bfloat162(h2, h3);
    __nv_bfloat162 l01 = __halves2bfloat162(l0, l1), l23 = __halves2bfloat162(l2, l3);
    h.x = *(uint32_t*)&h01; h.y = *(uint32_t*)&h23;
    l.x = *(uint32_t*)&l01; l.y = *(uint32_t*)&l23;
}

// ---- HMMA split-bf16 GEMM: C[M,N] = A[M,K] @ B[N,K]^T + bias (+resid) ----
// A,B fp32 in gmem; hi/lo bf16 split done during smem fill; hi*hi+hi*lo+lo*hi.
__global__ void __launch_bounds__(256, 2) gemm_mma(
    const float* __restrict__ A, const float* __restrict__ Bm,
    const float* __restrict__ bias, const float* __restrict__ resid,
    float* __restrict__ C, int M, int N, int K)
{
    __shared__ __nv_bfloat16 sAh[128 * SPITCH];
    __shared__ __nv_bfloat16 sAl[128 * SPITCH];
    __shared__ __nv_bfloat16 sBh[128 * SPITCH];
    __shared__ __nv_bfloat16 sBl[128 * SPITCH];

    const int tid = threadIdx.x;
    const int wid = tid >> 5;
    const int lane = tid & 31;
    const int row0 = blockIdx.y * 128;
    const int col0 = blockIdx.x * 128;
    const int warp_m = wid & 1;     // 2 x 64 rows
    const int warp_n = wid >> 1;    // 4 x 32 cols

    const uint32_t aAh = smem_u32(sAh), aAl = smem_u32(sAl);
    const uint32_t aBh = smem_u32(sBh), aBl = smem_u32(sBl);
    // ldmatrix lane address offsets (bytes)
    const uint32_t a_off = (uint32_t)(warp_m * 64 + (lane & 15)) * 80 + (uint32_t)(lane >> 4) * 16;
    const uint32_t b_off = (uint32_t)(warp_n * 32 + (lane & 7)) * 80 + (uint32_t)((lane >> 3) & 1) * 16;

    float acc[4][4][4];
    #pragma unroll
    for (int i = 0; i < 4; i++)
        #pragma unroll
        for (int j = 0; j < 4; j++)
            #pragma unroll
            for (int t = 0; t < 4; t++) acc[i][j][t] = 0.f;

    for (int kc0 = 0; kc0 < K; kc0 += 32) {
        __syncthreads();
        // fill A chunk [128 rows][32 k] -> hi/lo bf16, pitch 40
        #pragma unroll
        for (int i = 0; i < 4; i++) {
            int idx = tid + i * 256;           // 1024 float4 = 128 x 8
            int row = idx >> 3, q = idx & 7;
            float4 v = *(const float4*)(A + (size_t)(row0 + row) * K + kc0 + q * 4);
            uint2 h, l; cvt_split(v, h, l);
            *(uint2*)&sAh[row * SPITCH + q * 4] = h;
            *(uint2*)&sAl[row * SPITCH + q * 4] = l;
        }
        // fill B chunk
        #pragma unroll
        for (int i = 0; i < 4; i++) {
            int idx = tid + i * 256;
            int row = idx >> 3, q = idx & 7;
            float4 v = *(const float4*)(Bm + (size_t)(col0 + row) * K + kc0 + q * 4);
            uint2 h, l; cvt_split(v, h, l);
            *(uint2*)&sBh[row * SPITCH + q * 4] = h;
            *(uint2*)&sBl[row * SPITCH + q * 4] = l;
        }
        __syncthreads();

        #pragma unroll
        for (int ks = 0; ks < 2; ks++) {       // two k16 steps (byte offset ks*32)
            const uint32_t kb = ks * 32;
            uint32_t ah[4][4], al[4][4];
            #pragma unroll
            for (int mt = 0; mt < 4; mt++) {
                ldsm4(ah[mt], aAh + a_off + mt * (16 * 80) + kb);
                ldsm4(al[mt], aAl + a_off + mt * (16 * 80) + kb);
            }
            uint32_t bh[4][2], bl[4][2];
            #pragma unroll
            for (int nt = 0; nt < 4; nt++) {
                ldsm2(bh[nt], aBh + b_off + nt * (8 * 80) + kb);
                ldsm2(bl[nt], aBl + b_off + nt * (8 * 80) + kb);
            }
            #pragma unroll
            for (int mt = 0; mt < 4; mt++)
                #pragma unroll
                for (int nt = 0; nt < 4; nt++) {
                    mma16816(acc[mt][nt], ah[mt], bh[nt]);
                    mma16816(acc[mt][nt], ah[mt], bl[nt]);
                    mma16816(acc[mt][nt], al[mt], bh[nt]);
                }
        }
    }

    // epilogue: c0,c1 -> (row, col..col+1), c2,c3 -> (row+8, ...)
    const int lr = lane >> 2, lc = (lane & 3) * 2;
    #pragma unroll
    for (int mt = 0; mt < 4; mt++) {
        #pragma unroll
        for (int nt = 0; nt < 4; nt++) {
            const int gr = row0 + warp_m * 64 + mt * 16 + lr;
            const int gc = col0 + warp_n * 32 + nt * 8 + lc;
            const float b0 = bias[gc], b1 = bias[gc + 1];
            float2 o0, o1;
            o0.x = acc[mt][nt][0] + b0; o0.y = acc[mt][nt][1] + b1;
            o1.x = acc[mt][nt][2] + b0; o1.y = acc[mt][nt][3] + b1;
            if (resid) {
                float2 r0 = *(const float2*)(resid + (size_t)gr * N + gc);
                float2 r1 = *(const float2*)(resid + (size_t)(gr + 8) * N + gc);
                o0.x += r0.x; o0.y += r0.y;
                o1.x += r1.x; o1.y += r1.y;
            }
            *(float2*)(C + (size_t)gr * N + gc) = o0;
            *(float2*)(C + (size_t)(gr + 8) * N + gc) = o1;
        }
    }
}

// Fused attention per (q-tile of 32 rows, head, batch), 256 threads. (unchanged R13)
__global__ __launch_bounds__(256) void attn_kernel(
    const float* __restrict__ Qp, const float* __restrict__ Kp,
    const float* __restrict__ Vp, const float* __restrict__ mask,
    float* __restrict__ probs, float* __restrict__ ctx)
{
    extern __shared__ char dynsmem[];
    float* smem = (float*)dynsmem;
    float* Sm     = smem;                       // QT*LK = 32768
    float* Qs     = Sm + QT * LK;               // QT*QPITCH = 2176
    float* KVs    = Qs + QT * QPITCH;           // CK*KVPITCH = 17408
    float* red    = KVs + CK * KVPITCH;         // QT*HD = 2048
    float* rowinv = red + QT * HD;              // QT

    const int tid = threadIdx.x;
    const int q0 = blockIdx.x * QT;
    const int h  = blockIdx.y;
    const int b  = blockIdx.z;

    #pragma unroll
    for (int i = 0; i < 2; i++) {
        int idx4 = tid + i * 256;
        int r = idx4 >> 4, d = (idx4 & 15) * 4;
        float4 qv = *(const float4*)(Qp + (size_t)(b * LQ + q0 + r) * HIDDEN + h * HD + d);
        *(float4*)&Qs[r * QPITCH + d] = qv;
    }

    const int rg = tid >> 5;
    const int cg = tid & 31;

    for (int c0 = 0; c0 < LK; c0 += CK) {
        __syncthreads();
        #pragma unroll
        for (int i = 0; i < 16; i++) {
            int idx4 = tid + i * 256;
            int r = idx4 >> 4, d = (idx4 & 15) * 4;
            float4 kv = *(const float4*)(Kp + (size_t)(b * LK + c0 + r) * HIDDEN + h * HD + d);
            *(float4*)&KVs[r * KVPITCH + d] = kv;
        }
        __syncthreads();

        unsigned long long parts[4][8];
        #pragma unroll
        for (int i = 0; i < 4; i++)
            #pragma unroll
            for (int j = 0; j < 8; j++) parts[i][j] = 0ull;

        for (int d0 = 0; d0 < HD; d0 += 4) {
            F4U2 q4[4];
            #pragma unroll
            for (int i = 0; i < 4; i++)
                q4[i].f4 = *(const float4*)&Qs[(rg * 4 + i) * QPITCH + d0];
            #pragma unroll
            for (int j = 0; j < 8; j++) {
                F4U2 k4;
                k4.f4 = *(const float4*)&KVs[(cg + 32 * j) * KVPITCH + d0];
                #pragma unroll
                for (int i = 0; i < 4; i++) {
                    fma2(parts[i][j], q4[i].u[0], k4.u[0]);
                    fma2(parts[i][j], q4[i].u[1], k4.u[1]);
                }
            }
        }
        #pragma unroll
        for (int j = 0; j < 8; j++) {
            int c = c0 + cg + 32 * j;
            float mv = mask[b * LK + c];
            #pragma unroll
            for (int i = 0; i < 4; i++) {
                U2F2 u; u.u = parts[i][j];
                Sm[(rg * 4 + i) * LK + c] = (u.f[0] + u.f[1]) * 0.125f + mv;
            }
        }
    }
    __syncthreads();

    {
        const int w = tid >> 5, lane = tid & 31;
        #pragma unroll
        for (int rr = 0; rr < 4; rr++) {
            int r = w * 4 + rr;
            float m = -1e30f;
            #pragma unroll
            for (int c4 = lane; c4 < LK / 4; c4 += 32) {
                float4 v = *(const float4*)&Sm[r * LK + c4 * 4];
                m = fmaxf(m, fmaxf(fmaxf(v.x, v.y), fmaxf(v.z, v.w)));
            }
            #pragma unroll
            for (int off = 16; off; off >>= 1) m = fmaxf(m, __shfl_xor_sync(0xffffffffu, m, off));
            float s = 0.f;
            #pragma unroll
            for (int c4 = lane; c4 < LK / 4; c4 += 32) {
                float4 v = *(const float4*)&Sm[r * LK + c4 * 4];
                v.x = __expf(v.x - m); v.y = __expf(v.y - m);
                v.z = __expf(v.z - m); v.w = __expf(v.w - m);
                *(float4*)&Sm[r * LK + c4 * 4] = v;
                s += v.x + v.y + v.z + v.w;
            }
            #pragma unroll
            for (int off = 16; off; off >>= 1) s += __shfl_xor_sync(0xffffffffu, s, off);
            if (lane == 0) rowinv[r] = 1.f / s;
        }
    }
    __syncthreads();

    {
        float* prow = probs + ((size_t)((b * HEADS + h) * LQ + q0)) * LK;
        #pragma unroll
        for (int i4 = tid; i4 < QT * LK / 4; i4 += 256) {
            float inv = rowinv[i4 >> 8];
            float4 p = *(const float4*)&Sm[i4 * 4];
            p.x *= inv; p.y *= inv; p.z *= inv; p.w *= inv;
            *(float4*)&Sm[i4 * 4] = p;
            *(float4*)&prow[i4 * 4] = p;
        }
    }

    const int grp  = tid >> 7;
    const int gtid = tid & 127;
    const int rgv  = gtid >> 4;
    const int cgv  = gtid & 15;

    unsigned long long accv[4][2];
    #pragma unroll
    for (int i = 0; i < 4; i++) { accv[i][0] = 0ull; accv[i][1] = 0ull; }

    for (int c0 = 0; c0 < LK; c0 += CK) {
        __syncthreads();
        #pragma unroll
        for (int i = 0; i < 16; i++) {
            int idx4 = tid + i * 256;
            int r = idx4 >> 4, d = (idx4 & 15) * 4;
            float4 vv = *(const float4*)(Vp + (size_t)(b * LK + c0 + r) * HIDDEN + h * HD + d);
            *(float4*)&KVs[r * KVPITCH + d] = vv;
        }
        __syncthreads();

        const int kbase = grp * 128;
        for (int kk = 0; kk < 128; kk += 4) {
            F4U2 p4[4];
            #pragma unroll
            for (int i = 0; i < 4; i++)
                p4[i].f4 = *(const float4*)&Sm[(rgv * 4 + i) * LK + c0 + kbase + kk];
            #pragma unroll
            for (int t = 0; t < 4; t++) {
                F4U2 vv;
                vv.f4 = *(const float4*)&KVs[(kbase + kk + t) * KVPITCH + cgv * 4];
                #pragma unroll
                for (int i = 0; i < 4; i++) {
                    unsigned long long pd = dup2(p4[i].f[t]);
                    fma2(accv[i][0], pd, vv.u[0]);
                    fma2(accv[i][1], pd, vv.u[1]);
                }
            }
        }
    }
    __syncthreads();

    if (grp == 0) {
        #pragma unroll
        for (int i = 0; i < 4; i++) {
            U2F2 lo, hi; lo.u = accv[i][0]; hi.u = accv[i][1];
            float4 o; o.x = lo.f[0]; o.y = lo.f[1]; o.z = hi.f[0]; o.w = hi.f[1];
            *(float4*)&red[(rgv * 4 + i) * HD + cgv * 4] = o;
        }
    }
    __syncthreads();
    if (grp == 1) {
        #pragma unroll
        for (int i = 0; i < 4; i++) {
            U2F2 lo, hi; lo.u = accv[i][0]; hi.u = accv[i][1];
            float4 p = *(const float4*)&red[(rgv * 4 + i) * HD + cgv * 4];
            float4 o;
            o.x = lo.f[0] + p.x; o.y = lo.f[1] + p.y;
            o.z = hi.f[0] + p.z; o.w = hi.f[1] + p.w;
            *(float4*)(ctx + (size_t)(b * LQ + q0 + rgv * 4 + i) * HIDDEN + h * HD + cgv * 4) = o;
        }
    }
}

// Row LayerNorm over 768; one block of 256 threads per row.
__global__ void out_ln(const float* __restrict__ X, const float* __restrict__ gamma,
                       const float* __restrict__ beta, float* __restrict__ out)
{
    const int row = blockIdx.x;
    const int tid = threadIdx.x;
    const float* x = X + (size_t)row * HIDDEN;

    float v[3];
    float s = 0.f, s2 = 0.f;
    #pragma unroll
    for (int i = 0; i < 3; i++) {
        v[i] = x[tid + i * 256];
        s += v[i];
        s2 += v[i] * v[i];
    }
    const int w = tid >> 5, lane = tid & 31;
    #pragma unroll
    for (int off = 16; off; off >>= 1) {
        s  += __shfl_xor_sync(0xffffffffu, s,  off);
        s2 += __shfl_xor_sync(0xffffffffu, s2, off);
    }
    __shared__ float rs[8], rs2[8];
    __shared__ float mu_s, inv_s;
    if (lane == 0) { rs[w] = s; rs2[w] = s2; }
    __syncthreads();
    if (tid == 0) {
        float S = 0.f, S2 = 0.f;
        #pragma unroll
        for (int i = 0; i < 8; i++) { S += rs[i]; S2 += rs2[i]; }
        float mu = S * (1.0f / HIDDEN);
        float var = S2 * (1.0f / HIDDEN) - mu * mu;
        mu_s = mu;
        inv_s = rsqrtf(var + 1e-12f);
    }
    __syncthreads();
    const float mu = mu_s, inv = inv_s;
    #pragma unroll
    for (int i = 0; i < 3; i++) {
        int c = tid + i * 256;
        out[(size_t)row * HIDDEN + c] = (v[i] - mu) * inv * gamma[c] + beta[c];
    }
}

extern "C" void kernel_launch(void* const* d_in, const int* in_sizes, int n_in,
                              void* d_out, int out_size)
{
    const float* query = (const float*)d_in[0];
    const float* key   = (const float*)d_in[1];
    const float* value = (const float*)d_in[2];
    const float* mask  = (const float*)d_in[3];
    const float* Wq = (const float*)d_in[5];
    const float* bq = (const float*)d_in[6];
    const float* Wk = (const float*)d_in[7];
    const float* bk = (const float*)d_in[8];
    const float* Wv = (const float*)d_in[9];
    const float* bv = (const float*)d_in[10];
    const float* Wo = (const float*)d_in[11];
    const float* bo = (const float*)d_in[12];
    const float* gamma = (const float*)d_in[13];
    const float* beta  = (const float*)d_in[14];

    float* out   = (float*)d_out;
    float* probs = out + (size_t)BB * LQ * HIDDEN;

    float *qp, *kp, *vp, *ctx, *tmp;
    cudaGetSymbolAddress((void**)&qp,  g_q);
    cudaGetSymbolAddress((void**)&kp,  g_k);
    cudaGetSymbolAddress((void**)&vp,  g_v);
    cudaGetSymbolAddress((void**)&ctx, g_ctx);
    cudaGetSymbolAddress((void**)&tmp, g_tmp);

    // Q/K/V projections (HMMA split-bf16)
    gemm_mma<<<dim3(HIDDEN / 128, (BB * LQ) / 128), 256>>>(query, Wq, bq, nullptr, qp, BB * LQ, HIDDEN, HIDDEN);
    gemm_mma<<<dim3(HIDDEN / 128, (BB * LK) / 128), 256>>>(key,   Wk, bk, nullptr, kp, BB * LK, HIDDEN, HIDDEN);
    gemm_mma<<<dim3(HIDDEN / 128, (BB * LK) / 128), 256>>>(value, Wv, bv, nullptr, vp, BB * LK, HIDDEN, HIDDEN);

    // Fused attention (256 threads, ~213 KB smem)
    size_t smem = (size_t)(QT * LK + QT * QPITCH + CK * KVPITCH + QT * HD + QT) * sizeof(float);
    cudaFuncSetAttribute(attn_kernel, cudaFuncAttributeMaxDynamicSharedMemorySize, (int)smem);
    attn_kernel<<<dim3(LQ / QT, HEADS, BB), 256, smem>>>(qp, kp, vp, mask, probs, ctx);

    // Output projection + bias + residual, then LayerNorm
    gemm_mma<<<dim3(HIDDEN / 128, (BB * LQ) / 128), 256>>>(ctx, Wo, bo, query, tmp, BB * LQ, HIDDEN, HIDDEN);
    out_ln<<<BB * LQ, 256>>>(tmp, gamma, beta, out);
}

// round 17
// speedup vs baseline: 2.9113x; 1.0870x over previous
#include <cuda_runtime.h>
#include <cuda_bf16.h>
#include <cstdint>

#define HIDDEN 768
#define HEADS 12
#define HD 64
#define BB 8
#define LQ 512
#define LK 1024
#define QT 32

// mma GEMM tiling: 128x128 CTA tile, 8 warps (2 x 4), warp = 64x32, k-chunk 32
#define SPITCH 40            // smem row pitch in bf16 (80 B)

// attention smem pitches (bf16 elements)
#define KQP 72               // Q/K/V row pitch: 144 B (16-aligned)
#define PP 136               // P row pitch: 272 B (16-aligned)

// Scratch (allocation-free rule: __device__ globals)
__device__ float g_q[BB * LQ * HIDDEN];
__device__ float g_k[BB * LK * HIDDEN];
__device__ float g_v[BB * LK * HIDDEN];
__device__ float g_ctx[BB * LQ * HIDDEN];
__device__ float g_tmp[BB * LQ * HIDDEN];

__device__ __forceinline__ uint32_t smem_u32(const void* p)
{
    uint32_t a;
    asm("{ .reg .u64 t; cvta.to.shared.u64 t, %1; cvt.u32.u64 %0, t; }" : "=r"(a) : "l"(p));
    return a;
}

// ---- mma.sync helpers (legacy HMMA path; compiles for plain compute_103) ----
__device__ __forceinline__ void ldsm4(uint32_t* r, uint32_t addr)
{
    asm volatile("ldmatrix.sync.aligned.m8n8.x4.shared.b16 {%0,%1,%2,%3}, [%4];"
                 : "=r"(r[0]), "=r"(r[1]), "=r"(r[2]), "=r"(r[3]) : "r"(addr));
}
__device__ __forceinline__ void ldsm2(uint32_t* r, uint32_t addr)
{
    asm volatile("ldmatrix.sync.aligned.m8n8.x2.shared.b16 {%0,%1}, [%2];"
                 : "=r"(r[0]), "=r"(r[1]) : "r"(addr));
}
__device__ __forceinline__ void ldsm2t(uint32_t* r, uint32_t addr)
{
    asm volatile("ldmatrix.sync.aligned.m8n8.x2.trans.shared.b16 {%0,%1}, [%2];"
                 : "=r"(r[0]), "=r"(r[1]) : "r"(addr));
}
__device__ __forceinline__ void mma16816(float* d, const uint32_t* a, const uint32_t* b)
{
    asm volatile(
        "mma.sync.aligned.m16n8k16.row.col.f32.bf16.bf16.f32 "
        "{%0,%1,%2,%3}, {%4,%5,%6,%7}, {%8,%9}, {%0,%1,%2,%3};"
        : "+f"(d[0]), "+f"(d[1]), "+f"(d[2]), "+f"(d[3])
        : "r"(a[0]), "r"(a[1]), "r"(a[2]), "r"(a[3]), "r"(b[0]), "r"(b[1]));
}
__device__ __forceinline__ void cvt_split(float4 v, uint2& h, uint2& l)
{
    __nv_bfloat16 h0 = __float2bfloat16(v.x), h1 = __float2bfloat16(v.y);
    __nv_bfloat16 h2 = __float2bfloat16(v.z), h3 = __float2bfloat16(v.w);
    __nv_bfloat16 l0 = __float2bfloat16(v.x - __bfloat162float(h0));
    __nv_bfloat16 l1 = __float2bfloat16(v.y - __bfloat162float(h1));
    __nv_bfloat16 l2 = __float2bfloat16(v.z - __bfloat162float(h2));
    __nv_bfloat16 l3 = __float2bfloat16(v.w - __bfloat162float(h3));
    __nv_bfloat162 h01 = __halves2bfloat162(h0, h1), h23 = __halves2bfloat162(h2, h3);
    __nv_bfloat162 l01 = __halves2bfloat162(l0, l1), l23 = __halves2bfloat162(l2, l3);
    h.x = *(uint32_t*)&h01; h.y = *(uint32_t*)&h23;
    l.x = *(uint32_t*)&l01; l.y = *(uint32_t*)&l23;
}

// ---- HMMA split-bf16 GEMM: C[M,N] = A[M,K] @ B[N,K]^T + bias (+resid) ----
__global__ void __launch_bounds__(256, 2) gemm_mma(
    const float* __restrict__ A, const float* __restrict__ Bm,
    const float* __restrict__ bias, const float* __restrict__ resid,
    float* __restrict__ C, int M, int N, int K)
{
    __shared__ __nv_bfloat16 sAh[128 * SPITCH];
    __shared__ __nv_bfloat16 sAl[128 * SPITCH];
    __shared__ __nv_bfloat16 sBh[128 * SPITCH];
    __shared__ __nv_bfloat16 sBl[128 * SPITCH];

    const int tid = threadIdx.x;
    const int wid = tid >> 5;
    const int lane = tid & 31;
    const int row0 = blockIdx.y * 128;
    const int col0 = blockIdx.x * 128;
    const int warp_m = wid & 1;
    const int warp_n = wid >> 1;

    const uint32_t aAh = smem_u32(sAh), aAl = smem_u32(sAl);
    const uint32_t aBh = smem_u32(sBh), aBl = smem_u32(sBl);
    const uint32_t a_off = (uint32_t)(warp_m * 64 + (lane & 15)) * 80 + (uint32_t)(lane >> 4) * 16;
    const uint32_t b_off = (uint32_t)(warp_n * 32 + (lane & 7)) * 80 + (uint32_t)((lane >> 3) & 1) * 16;

    float acc[4][4][4];
    #pragma unroll
    for (int i = 0; i < 4; i++)
        #pragma unroll
        for (int j = 0; j < 4; j++)
            #pragma unroll
            for (int t = 0; t < 4; t++) acc[i][j][t] = 0.f;

    for (int kc0 = 0; kc0 < K; kc0 += 32) {
        __syncthreads();
        #pragma unroll
        for (int i = 0; i < 4; i++) {
            int idx = tid + i * 256;
            int row = idx >> 3, q = idx & 7;
            float4 v = *(const float4*)(A + (size_t)(row0 + row) * K + kc0 + q * 4);
            uint2 h, l; cvt_split(v, h, l);
            *(uint2*)&sAh[row * SPITCH + q * 4] = h;
            *(uint2*)&sAl[row * SPITCH + q * 4] = l;
        }
        #pragma unroll
        for (int i = 0; i < 4; i++) {
            int idx = tid + i * 256;
            int row = idx >> 3, q = idx & 7;
            float4 v = *(const float4*)(Bm + (size_t)(col0 + row) * K + kc0 + q * 4);
            uint2 h, l; cvt_split(v, h, l);
            *(uint2*)&sBh[row * SPITCH + q * 4] = h;
            *(uint2*)&sBl[row * SPITCH + q * 4] = l;
        }
        __syncthreads();

        #pragma unroll
        for (int ks = 0; ks < 2; ks++) {
            const uint32_t kb = ks * 32;
            uint32_t ah[4][4], al[4][4];
            #pragma unroll
            for (int mt = 0; mt < 4; mt++) {
                ldsm4(ah[mt], aAh + a_off + mt * (16 * 80) + kb);
                ldsm4(al[mt], aAl + a_off + mt * (16 * 80) + kb);
            }
            uint32_t bh[4][2], bl[4][2];
            #pragma unroll
            for (int nt = 0; nt < 4; nt++) {
                ldsm2(bh[nt], aBh + b_off + nt * (8 * 80) + kb);
                ldsm2(bl[nt], aBl + b_off + nt * (8 * 80) + kb);
            }
            #pragma unroll
            for (int mt = 0; mt < 4; mt++)
                #pragma unroll
                for (int nt = 0; nt < 4; nt++) {
                    mma16816(acc[mt][nt], ah[mt], bh[nt]);
                    mma16816(acc[mt][nt], ah[mt], bl[nt]);
                    mma16816(acc[mt][nt], al[mt], bh[nt]);
                }
        }
    }

    const int lr = lane >> 2, lc = (lane & 3) * 2;
    #pragma unroll
    for (int mt = 0; mt < 4; mt++) {
        #pragma unroll
        for (int nt = 0; nt < 4; nt++) {
            const int gr = row0 + warp_m * 64 + mt * 16 + lr;
            const int gc = col0 + warp_n * 32 + nt * 8 + lc;
            const float b0 = bias[gc], b1 = bias[gc + 1];
            float2 o0, o1;
            o0.x = acc[mt][nt][0] + b0; o0.y = acc[mt][nt][1] + b1;
            o1.x = acc[mt][nt][2] + b0; o1.y = acc[mt][nt][3] + b1;
            if (resid) {
                float2 r0 = *(const float2*)(resid + (size_t)gr * N + gc);
                float2 r1 = *(const float2*)(resid + (size_t)(gr + 8) * N + gc);
                o0.x += r0.x; o0.y += r0.y;
                o1.x += r1.x; o1.y += r1.y;
            }
            *(float2*)(C + (size_t)gr * N + gc) = o0;
            *(float2*)(C + (size_t)(gr + 8) * N + gc) = o1;
        }
    }
}

// ---- Fused attention on HMMA: per (q-tile 32, head, batch), 256 threads ----
// scores (QK^T split-bf16 mma) -> softmax fp32 -> probs write -> ctx = P@V (split-bf16 mma)
__global__ __launch_bounds__(256) void attn_kernel(
    const float* __restrict__ Qp, const float* __restrict__ Kp,
    const float* __restrict__ Vp, const float* __restrict__ mask,
    float* __restrict__ probs, float* __restrict__ ctx)
{
    extern __shared__ char dynsmem[];
    float* Sm     = (float*)dynsmem;                 // 32x1024 fp32
    float* msk    = Sm + QT * LK;                    // 1024
    float* rowinv = msk + LK;                        // 32
    char* bfb = dynsmem + 135296;                    // 16B-aligned bf16 region
    __nv_bfloat16* Qh = (__nv_bfloat16*)bfb;         // 32 x 72
    __nv_bfloat16* Ql = Qh + 32 * KQP;
    __nv_bfloat16* Kh = Ql + 32 * KQP;               // 128 x 72 (reused for V)
    __nv_bfloat16* Kl = Kh + 128 * KQP;
    __nv_bfloat16* Ph = Kl + 128 * KQP;              // 32 x 136
    __nv_bfloat16* Pl = Ph + 32 * PP;

    const int tid = threadIdx.x;
    const int lane = tid & 31;
    const int w = tid >> 5;
    const int q0 = blockIdx.x * QT;
    const int h  = blockIdx.y;
    const int b  = blockIdx.z;

    const uint32_t aQh = smem_u32(Qh), aQl = smem_u32(Ql);
    const uint32_t aKh = smem_u32(Kh), aKl = smem_u32(Kl);
    const uint32_t aPh = smem_u32(Ph), aPl = smem_u32(Pl);

    // ldmatrix lane offsets (bytes)
    const uint32_t qoff = (uint32_t)(lane & 15) * 144 + (uint32_t)(lane >> 4) * 16;
    const uint32_t koff = (uint32_t)(w * 16 + (lane & 7)) * 144 + (uint32_t)((lane >> 3) & 1) * 16;
    const uint32_t voff = (uint32_t)(lane & 15) * 144 + (uint32_t)w * 16;
    const uint32_t poff = (uint32_t)(lane & 15) * 272 + (uint32_t)(lane >> 4) * 16;
    const int lr = lane >> 2, lc = (lane & 3) * 2;

    // stage mask + Q (hi/lo bf16)
    for (int i = tid; i < LK; i += 256) msk[i] = mask[b * LK + i];
    #pragma unroll
    for (int i = 0; i < 2; i++) {
        int idx4 = tid + i * 256;                    // 512 float4 = 32x64
        int r = idx4 >> 4, d = (idx4 & 15) * 4;
        float4 v = *(const float4*)(Qp + (size_t)(b * LQ + q0 + r) * HIDDEN + h * HD + d);
        uint2 hh, ll; cvt_split(v, hh, ll);
        *(uint2*)&Qh[r * KQP + d] = hh;
        *(uint2*)&Ql[r * KQP + d] = ll;
    }

    // ================= scores: warp w owns cols [w*16, w*16+16) of each 128-chunk =================
    for (int c0 = 0; c0 < LK; c0 += 128) {
        __syncthreads();
        #pragma unroll
        for (int i = 0; i < 8; i++) {
            int idx4 = tid + i * 256;                // 2048 float4 = 128x64
            int r = idx4 >> 4, d = (idx4 & 15) * 4;
            float4 v = *(const float4*)(Kp + (size_t)(b * LK + c0 + r) * HIDDEN + h * HD + d);
            uint2 hh, ll; cvt_split(v, hh, ll);
            *(uint2*)&Kh[r * KQP + d] = hh;
            *(uint2*)&Kl[r * KQP + d] = ll;
        }
        __syncthreads();

        float acc[2][2][4];
        #pragma unroll
        for (int mt = 0; mt < 2; mt++)
            #pragma unroll
            for (int nt = 0; nt < 2; nt++)
                #pragma unroll
                for (int t = 0; t < 4; t++) acc[mt][nt][t] = 0.f;

        #pragma unroll
        for (int ks = 0; ks < 4; ks++) {
            const uint32_t kb = ks * 32;
            uint32_t ah[2][4], al[2][4], bh[2][2], bl[2][2];
            #pragma unroll
            for (int mt = 0; mt < 2; mt++) {
                ldsm4(ah[mt], aQh + qoff + mt * (16 * 144) + kb);
                ldsm4(al[mt], aQl + qoff + mt * (16 * 144) + kb);
            }
            #pragma unroll
            for (int nt = 0; nt < 2; nt++) {
                ldsm2(bh[nt], aKh + koff + nt * (8 * 144) + kb);
                ldsm2(bl[nt], aKl + koff + nt * (8 * 144) + kb);
            }
            #pragma unroll
            for (int mt = 0; mt < 2; mt++)
                #pragma unroll
                for (int nt = 0; nt < 2; nt++) {
                    mma16816(acc[mt][nt], ah[mt], bh[nt]);
                    mma16816(acc[mt][nt], ah[mt], bl[nt]);
                    mma16816(acc[mt][nt], al[mt], bh[nt]);
                }
        }
        // fragments -> Sm with scale + mask
        #pragma unroll
        for (int mt = 0; mt < 2; mt++)
            #pragma unroll
            for (int nt = 0; nt < 2; nt++) {
                int row = mt * 16 + lr;
                int c = c0 + w * 16 + nt * 8 + lc;
                Sm[row * LK + c]           = acc[mt][nt][0] * 0.125f + msk[c];
                Sm[row * LK + c + 1]       = acc[mt][nt][1] * 0.125f + msk[c + 1];
                Sm[(row + 8) * LK + c]     = acc[mt][nt][2] * 0.125f + msk[c];
                Sm[(row + 8) * LK + c + 1] = acc[mt][nt][3] * 0.125f + msk[c + 1];
            }
    }
    __syncthreads();

    // ---- softmax: warp w owns rows 4w..4w+3 (fp32, exact) ----
    {
        #pragma unroll
        for (int rr = 0; rr < 4; rr++) {
            int r = w * 4 + rr;
            float m = -1e30f;
            #pragma unroll
            for (int c4 = lane; c4 < LK / 4; c4 += 32) {
                float4 v = *(const float4*)&Sm[r * LK + c4 * 4];
                m = fmaxf(m, fmaxf(fmaxf(v.x, v.y), fmaxf(v.z, v.w)));
            }
            #pragma unroll
            for (int off = 16; off; off >>= 1) m = fmaxf(m, __shfl_xor_sync(0xffffffffu, m, off));
            float s = 0.f;
            #pragma unroll
            for (int c4 = lane; c4 < LK / 4; c4 += 32) {
                float4 v = *(const float4*)&Sm[r * LK + c4 * 4];
                v.x = __expf(v.x - m); v.y = __expf(v.y - m);
                v.z = __expf(v.z - m); v.w = __expf(v.w - m);
                *(float4*)&Sm[r * LK + c4 * 4] = v;
                s += v.x + v.y + v.z + v.w;
            }
            #pragma unroll
            for (int off = 16; off; off >>= 1) s += __shfl_xor_sync(0xffffffffu, s, off);
            if (lane == 0) rowinv[r] = 1.f / s;
        }
    }
    __syncthreads();

    // ---- normalize + write probs (fp32, coalesced) ----
    {
        float* prow = probs + ((size_t)((b * HEADS + h) * LQ + q0)) * LK;
        #pragma unroll
        for (int i4 = tid; i4 < QT * LK / 4; i4 += 256) {
            float inv = rowinv[i4 >> 8];
            float4 p = *(const float4*)&Sm[i4 * 4];
            p.x *= inv; p.y *= inv; p.z *= inv; p.w *= inv;
            *(float4*)&Sm[i4 * 4] = p;
            *(float4*)&prow[i4 * 4] = p;
        }
    }

    // ================= ctx = P @ V : warp w owns d cols [w*8, w*8+8) =================
    float accv[2][4];
    #pragma unroll
    for (int mt = 0; mt < 2; mt++)
        #pragma unroll
        for (int t = 0; t < 4; t++) accv[mt][t] = 0.f;

    for (int c0 = 0; c0 < LK; c0 += 128) {
        __syncthreads();
        // fill V chunk (reuse K buffers)
        #pragma unroll
        for (int i = 0; i < 8; i++) {
            int idx4 = tid + i * 256;
            int r = idx4 >> 4, d = (idx4 & 15) * 4;
            float4 v = *(const float4*)(Vp + (size_t)(b * LK + c0 + r) * HIDDEN + h * HD + d);
            uint2 hh, ll; cvt_split(v, hh, ll);
            *(uint2*)&Kh[r * KQP + d] = hh;
            *(uint2*)&Kl[r * KQP + d] = ll;
        }
        // convert P slice [32][128] -> bf16 hi/lo
        #pragma unroll
        for (int i = 0; i < 4; i++) {
            int idx4 = tid + i * 256;                // 1024 float4 = 32 x 32
            int r = idx4 >> 5, q = (idx4 & 31) * 4;
            float4 p = *(const float4*)&Sm[r * LK + c0 + q];
            uint2 hh, ll; cvt_split(p, hh, ll);
            *(uint2*)&Ph[r * PP + q] = hh;
            *(uint2*)&Pl[r * PP + q] = ll;
        }
        __syncthreads();

        #pragma unroll
        for (int ks = 0; ks < 8; ks++) {
            uint32_t ph[2][4], pl[2][4], vh[2], vl[2];
            #pragma unroll
            for (int mt = 0; mt < 2; mt++) {
                ldsm4(ph[mt], aPh + poff + mt * (16 * 272) + ks * 32);
                ldsm4(pl[mt], aPl + poff + mt * (16 * 272) + ks * 32);
            }
            ldsm2t(vh, aKh + voff + ks * (16 * 144));
            ldsm2t(vl, aKl + voff + ks * (16 * 144));
            #pragma unroll
            for (int mt = 0; mt < 2; mt++) {
                mma16816(accv[mt], ph[mt], vh);
                mma16816(accv[mt], ph[mt], vl);
                mma16816(accv[mt], pl[mt], vh);
            }
        }
    }

    // write ctx fragments
    #pragma unroll
    for (int mt = 0; mt < 2; mt++) {
        const int row = q0 + mt * 16 + lr;
        const int col = h * HD + w * 8 + lc;
        float2 o0, o1;
        o0.x = accv[mt][0]; o0.y = accv[mt][1];
        o1.x = accv[mt][2]; o1.y = accv[mt][3];
        *(float2*)(ctx + (size_t)(b * LQ + row) * HIDDEN + col) = o0;
        *(float2*)(ctx + (size_t)(b * LQ + row + 8) * HIDDEN + col) = o1;
    }
}

// Row LayerNorm over 768; one block of 256 threads per row.
__global__ void out_ln(const float* __restrict__ X, const float* __restrict__ gamma,
                       const float* __restrict__ beta, float* __restrict__ out)
{
    const int row = blockIdx.x;
    const int tid = threadIdx.x;
    const float* x = X + (size_t)row * HIDDEN;

    float v[3];
    float s = 0.f, s2 = 0.f;
    #pragma unroll
    for (int i = 0; i < 3; i++) {
        v[i] = x[tid + i * 256];
        s += v[i];
        s2 += v[i] * v[i];
    }
    const int w = tid >> 5, lane = tid & 31;
    #pragma unroll
    for (int off = 16; off; off >>= 1) {
        s  += __shfl_xor_sync(0xffffffffu, s,  off);
        s2 += __shfl_xor_sync(0xffffffffu, s2, off);
    }
    __shared__ float rs[8], rs2[8];
    __shared__ float mu_s, inv_s;
    if (lane == 0) { rs[w] = s; rs2[w] = s2; }
    __syncthreads();
    if (tid == 0) {
        float S = 0.f, S2 = 0.f;
        #pragma unroll
        for (int i = 0; i < 8; i++) { S += rs[i]; S2 += rs2[i]; }
        float mu = S * (1.0f / HIDDEN);
        float var = S2 * (1.0f / HIDDEN) - mu * mu;
        mu_s = mu;
        inv_s = rsqrtf(var + 1e-12f);
    }
    __syncthreads();
    const float mu = mu_s, inv = inv_s;
    #pragma unroll
    for (int i = 0; i < 3; i++) {
        int c = tid + i * 256;
        out[(size_t)row * HIDDEN + c] = (v[i] - mu) * inv * gamma[c] + beta[c];
    }
}

extern "C" void kernel_launch(void* const* d_in, const int* in_sizes, int n_in,
                              void* d_out, int out_size)
{
    const float* query = (const float*)d_in[0];
    const float* key   = (const float*)d_in[1];
    const float* value = (const float*)d_in[2];
    const float* mask  = (const float*)d_in[3];
    const float* Wq = (const float*)d_in[5];
    const float* bq = (const float*)d_in[6];
    const float* Wk = (const float*)d_in[7];
    const float* bk = (const float*)d_in[8];
    const float* Wv = (const float*)d_in[9];
    const float* bv = (const float*)d_in[10];
    const float* Wo = (const float*)d_in[11];
    const float* bo = (const float*)d_in[12];
    const float* gamma = (const float*)d_in[13];
    const float* beta  = (const float*)d_in[14];

    float* out   = (float*)d_out;
    float* probs = out + (size_t)BB * LQ * HIDDEN;

    float *qp, *kp, *vp, *ctx, *tmp;
    cudaGetSymbolAddress((void**)&qp,  g_q);
    cudaGetSymbolAddress((void**)&kp,  g_k);
    cudaGetSymbolAddress((void**)&vp,  g_v);
    cudaGetSymbolAddress((void**)&ctx, g_ctx);
    cudaGetSymbolAddress((void**)&tmp, g_tmp);

    // Q/K/V projections (HMMA split-bf16)
    gemm_mma<<<dim3(HIDDEN / 128, (BB * LQ) / 128), 256>>>(query, Wq, bq, nullptr, qp, BB * LQ, HIDDEN, HIDDEN);
    gemm_mma<<<dim3(HIDDEN / 128, (BB * LK) / 128), 256>>>(key,   Wk, bk, nullptr, kp, BB * LK, HIDDEN, HIDDEN);
    gemm_mma<<<dim3(HIDDEN / 128, (BB * LK) / 128), 256>>>(value, Wv, bv, nullptr, vp, BB * LK, HIDDEN, HIDDEN);

    // Fused attention on HMMA (~194 KB dyn smem)
    size_t smem = 135296                     // Sm + msk + rowinv (fp32)
                + 2 * 32 * KQP * 2           // Qh/Ql
                + 2 * 128 * KQP * 2          // Kh/Kl (V reuse)
                + 2 * 32 * PP * 2;           // Ph/Pl
    cudaFuncSetAttribute(attn_kernel, cudaFuncAttributeMaxDynamicSharedMemorySize, (int)smem);
    attn_kernel<<<dim3(LQ / QT, HEADS, BB), 256, smem>>>(qp, kp, vp, mask, probs, ctx);

    // Output projection + bias + residual, then LayerNorm
    gemm_mma<<<dim3(HIDDEN / 128, (BB * LQ) / 128), 256>>>(ctx, Wo, bo, query, tmp, BB * LQ, HIDDEN, HIDDEN);
    out_ln<<<BB * LQ, 256>>>(tmp, gamma, beta, out);
}